// round 1
// baseline (speedup 1.0000x reference)
#include <cuda_runtime.h>
#include <math.h>

#define Bb 2
#define Tt 2048
#define Cc 768
#define Hh 12

static const long long CTll  = (long long)Cc * Tt;          // 1572864 per-batch (C,T) plane
static const long long BTCll = (long long)Bb * Tt * Cc;     // 3145728 full (B,T,C) tensor

// ---------------- workspace (single device symbol) ----------------
// layout (floats):
//  TM   : (B,384,T)                     @ 0          size 1572864
//  XB[6]: (B,C,T) each (xr,xw,xk,xv,xa,xg) @ 1572864  size 6*3145728
//  H1   : (B,192,T) lora stage1 scratch @ 20447232   size 786432
//  RIN  : 6 x (B,T,C) (r,w,k,v,am,bm)   @ 21233664   size 6*3145728
//  KL   : (B,T,C)                       @ 40108032
//  AS   : (B,T,C)                       @ 43253760
//  GT   : (B,T,C)                       @ 46399488
//  Y    : (B,T,C)                       @ 49545216
//  YG   : (B,T,C)                       @ 52690944
//  total 55836672 floats (~223 MB)
#define WS_TM 0LL
#define WS_XB 1572864LL
#define WS_H1 20447232LL
#define WS_RIN 21233664LL
#define WS_KL 40108032LL
#define WS_AS 43253760LL
#define WS_GT 46399488LL
#define WS_Y  49545216LL
#define WS_YG 52690944LL
__device__ float g_ws[55836672];

// ---------------- generic tiled SGEMM with epilogues ----------------
enum { EPI_NONE = 0, EPI_TANH = 1, EPI_MIX = 2, EPI_DECAY = 3, EPI_SIG = 4 };

__global__ __launch_bounds__(256) void gemm_k(
    const float* __restrict__ A, int sAM, int sAK, long long bsA,
    const float* __restrict__ Bm, int sBK, int sBN, long long bsB,
    float* __restrict__ O, int sOM, int sON, long long bsO,
    int M, int N, int K, int epi,
    const float* __restrict__ aux1,
    const float* __restrict__ aux2, long long bsAux2)
{
    int bz = blockIdx.z;
    A  += (long long)bz * bsA;
    Bm += (long long)bz * bsB;
    O  += (long long)bz * bsO;
    const float* x2 = aux2 ? (aux2 + (long long)bz * bsAux2) : (const float*)0;

    __shared__ __align__(16) float As[16][68];
    __shared__ __align__(16) float Bs[16][68];

    int tid = threadIdx.x;
    int tx = tid & 15, ty = tid >> 4;
    int m0 = blockIdx.y * 64, n0 = blockIdx.x * 64;

    float acc[4][4];
#pragma unroll
    for (int i = 0; i < 4; i++)
#pragma unroll
        for (int j = 0; j < 4; j++) acc[i][j] = 0.f;

    for (int k0 = 0; k0 < K; k0 += 16) {
        // --- load A tile (64 rows m x 16 cols k) ---
        if (sAK == 1) {
            int m = tid >> 2, kq = (tid & 3) << 2;
            float4 v = *reinterpret_cast<const float4*>(A + (long long)(m0 + m) * sAM + (k0 + kq));
            As[kq + 0][m] = v.x; As[kq + 1][m] = v.y; As[kq + 2][m] = v.z; As[kq + 3][m] = v.w;
        } else { // sAM == 1 (column-major A)
            int k = tid >> 4, mq = (tid & 15) << 2;
            float4 v = *reinterpret_cast<const float4*>(A + (long long)(k0 + k) * sAK + (m0 + mq));
            As[k][mq + 0] = v.x; As[k][mq + 1] = v.y; As[k][mq + 2] = v.z; As[k][mq + 3] = v.w;
        }
        // --- load B tile (16 x 64) ---
        if (sBN == 1) {
            int k = tid >> 4, nq = (tid & 15) << 2;
            float4 v = *reinterpret_cast<const float4*>(Bm + (long long)(k0 + k) * sBK + (n0 + nq));
            Bs[k][nq + 0] = v.x; Bs[k][nq + 1] = v.y; Bs[k][nq + 2] = v.z; Bs[k][nq + 3] = v.w;
        } else { // sBK == 1
            int n = tid >> 2, kq = (tid & 3) << 2;
            float4 v = *reinterpret_cast<const float4*>(Bm + (long long)(n0 + n) * sBN + (k0 + kq));
            Bs[kq + 0][n] = v.x; Bs[kq + 1][n] = v.y; Bs[kq + 2][n] = v.z; Bs[kq + 3][n] = v.w;
        }
        __syncthreads();
#pragma unroll
        for (int k = 0; k < 16; k++) {
            float4 av = *reinterpret_cast<const float4*>(&As[k][ty << 2]);
            float4 bv = *reinterpret_cast<const float4*>(&Bs[k][tx << 2]);
            float a_[4] = {av.x, av.y, av.z, av.w};
            float b_[4] = {bv.x, bv.y, bv.z, bv.w};
#pragma unroll
            for (int i = 0; i < 4; i++)
#pragma unroll
                for (int j = 0; j < 4; j++)
                    acc[i][j] = fmaf(a_[i], b_[j], acc[i][j]);
        }
        __syncthreads();
    }

#pragma unroll
    for (int i = 0; i < 4; i++) {
        int m = m0 + (ty << 2) + i;
#pragma unroll
        for (int j = 0; j < 4; j++) {
            int n = n0 + (tx << 2) + j;
            float v = acc[i][j];
            if (epi == EPI_TANH) {
                v = tanhf(v);
            } else if (epi == EPI_MIX) {
                v = x2[(long long)m * N + n] * (1.f + aux1[m] + v);
            } else if (epi == EPI_DECAY) {
                float u = -(aux1[m] + v);
                float sp = fmaxf(u, 0.f) + log1pf(expf(-fabsf(u)));   // softplus(u)
                v = expf(-expf(-sp - 0.5f));                          // exp(-exp(wlog))
            } else if (epi == EPI_SIG) {
                v = 1.f / (1.f + expf(-(aux1[m] + v)));
            }
            O[(long long)m * sOM + (long long)n * sON] = v;
        }
    }
}

// ---------------- E1: kk normalize, build a/b mats ----------------
__global__ __launch_bounds__(256) void e1_k(
    const float* __restrict__ kc, const float* __restrict__ kl,
    const float* __restrict__ asig, float* __restrict__ am, float* __restrict__ bm)
{
    int gw = (int)((blockIdx.x * blockDim.x + threadIdx.x) >> 5); // (b*T + t)*H + h
    int lane = threadIdx.x & 31;
    long long base = (long long)gw * 64;
    float k1 = kc[base + lane]      + kl[base + lane];
    float k2 = kc[base + lane + 32] + kl[base + lane + 32];
    float ss = k1 * k1 + k2 * k2;
#pragma unroll
    for (int o = 16; o; o >>= 1) ss += __shfl_xor_sync(0xffffffffu, ss, o);
    float inv = 1.f / fmaxf(sqrtf(ss), 1e-12f);
    float n1 = k1 * inv, n2 = k2 * inv;
    am[base + lane]      = -n1;
    am[base + lane + 32] = -n2;
    bm[base + lane]      = n1 * asig[base + lane];
    bm[base + lane + 32] = n2 * asig[base + lane + 32];
}

// ---------------- WKV7 recurrence ----------------
// grid = B*H*RS, block = 16 rows x 4 j-chunks = 64 threads, 16 state regs/thread.
#define RS 4
__global__ __launch_bounds__(64) void wkv7_k(const float* __restrict__ rin, float* __restrict__ y)
{
    int blk = blockIdx.x;
    int rs = blk % RS;
    int bh = blk / RS;
    int b = bh / Hh, h = bh % Hh;
    long long base = (long long)b * Tt * Cc + (long long)h * 64;

    int tid = threadIdx.x;
    int lr = tid >> 2, jc = tid & 3;
    int i = rs * 16 + lr;          // global row in [0,64)
    int jbase = jc << 4;

    __shared__ __align__(16) float sh[2][384];  // [buf][vec*64 + j], vec: r,w,k,v,a,b

    // preload step 0 (each thread loads 6 coalesced floats)
    {
        long long off = base;
#pragma unroll
        for (int q = 0; q < 6; q++)
            sh[0][q * 64 + tid] = rin[(long long)q * BTCll + off + tid];
    }
    __syncthreads();

    float S[16];
#pragma unroll
    for (int u = 0; u < 16; u++) S[u] = 0.f;

    for (int t = 0; t < Tt; t++) {
        int cur = t & 1, nxt = cur ^ 1;
        // prefetch t+1 into registers (no sync needed)
        float pf[6];
        if (t + 1 < Tt) {
            long long off = base + (long long)(t + 1) * Cc;
#pragma unroll
            for (int q = 0; q < 6; q++)
                pf[q] = rin[(long long)q * BTCll + off + tid];
        } else {
#pragma unroll
            for (int q = 0; q < 6; q++) pf[q] = 0.f;
        }

        const float* sb = &sh[cur][0];
        // sa_i = sum_j S[i][j] * a[j]
        float sa = 0.f;
        const float4* ap = reinterpret_cast<const float4*>(sb + 4 * 64 + jbase);
#pragma unroll
        for (int q = 0; q < 4; q++) {
            float4 av = ap[q];
            sa = fmaf(S[4 * q + 0], av.x, fmaf(S[4 * q + 1], av.y,
                 fmaf(S[4 * q + 2], av.z, fmaf(S[4 * q + 3], av.w, sa))));
        }
        sa += __shfl_xor_sync(0xffffffffu, sa, 1);
        sa += __shfl_xor_sync(0xffffffffu, sa, 2);

        float vi = sb[3 * 64 + i];
        const float4* rp = reinterpret_cast<const float4*>(sb + 0 * 64 + jbase);
        const float4* wp = reinterpret_cast<const float4*>(sb + 1 * 64 + jbase);
        const float4* kp = reinterpret_cast<const float4*>(sb + 2 * 64 + jbase);
        const float4* bp = reinterpret_cast<const float4*>(sb + 5 * 64 + jbase);
        float yv = 0.f;
#pragma unroll
        for (int q = 0; q < 4; q++) {
            float4 wv = wp[q], kv = kp[q], bv = bp[q], rv = rp[q];
            S[4*q+0] = fmaf(S[4*q+0], wv.x, fmaf(sa, bv.x, vi * kv.x));
            yv = fmaf(S[4*q+0], rv.x, yv);
            S[4*q+1] = fmaf(S[4*q+1], wv.y, fmaf(sa, bv.y, vi * kv.y));
            yv = fmaf(S[4*q+1], rv.y, yv);
            S[4*q+2] = fmaf(S[4*q+2], wv.z, fmaf(sa, bv.z, vi * kv.z));
            yv = fmaf(S[4*q+2], rv.z, yv);
            S[4*q+3] = fmaf(S[4*q+3], wv.w, fmaf(sa, bv.w, vi * kv.w));
            yv = fmaf(S[4*q+3], rv.w, yv);
        }
        yv += __shfl_xor_sync(0xffffffffu, yv, 1);
        yv += __shfl_xor_sync(0xffffffffu, yv, 2);
        if (jc == 0)
            y[base + (long long)t * Cc + i] = yv;

        // stage t+1 into the other buffer
        float* sn = &sh[nxt][0];
#pragma unroll
        for (int q = 0; q < 6; q++)
            sn[q * 64 + tid] = pf[q];
        __syncthreads();
    }
}

// ---------------- E2: RMSNorm + rk*v + gate ----------------
__global__ __launch_bounds__(768) void e2_k(
    const float* __restrict__ y,
    const float* __restrict__ rr, const float* __restrict__ kk, const float* __restrict__ vv,
    const float* __restrict__ gg, const float* __restrict__ faaaa,
    const float* __restrict__ lnw, float* __restrict__ yg)
{
    long long base = (long long)blockIdx.x * Cc;
    int c = threadIdx.x;
    int w = c >> 5, h = c >> 6, j = c & 63, lane = c & 31;
    float yv = y[base + c];
    float rv = rr[base + c], kv = kk[base + c], vV = vv[base + c];
    float s1 = yv * yv;
    float s2 = rv * kv * faaaa[h * 64 + j];
#pragma unroll
    for (int o = 16; o; o >>= 1) {
        s1 += __shfl_xor_sync(0xffffffffu, s1, o);
        s2 += __shfl_xor_sync(0xffffffffu, s2, o);
    }
    __shared__ float sh1[24], sh2[24];
    if (lane == 0) { sh1[w] = s1; sh2[w] = s2; }
    __syncthreads();
    float tot = 0.f;
#pragma unroll
    for (int q = 0; q < 24; q++) tot += sh1[q];
    float scale = rsqrtf(tot * (1.f / 768.f) + 1e-5f);
    float rk = sh2[h * 2] + sh2[h * 2 + 1];
    float yo = yv * scale * lnw[c] + rk * vV;
    yg[base + c] = yo * gg[base + c];
}

// ---------------- launch ----------------
extern "C" void kernel_launch(void* const* d_in, const int* in_sizes, int n_in,
                              void* d_out, int out_size)
{
    (void)in_sizes; (void)n_in; (void)out_size;
    const float* x       = (const float*)d_in[0];
    const float* tmaa_r  = (const float*)d_in[2];
    const float* tmaa_w  = (const float*)d_in[3];
    const float* tmaa_k  = (const float*)d_in[4];
    const float* tmaa_v  = (const float*)d_in[5];
    const float* tmaa_a  = (const float*)d_in[6];
    const float* tmaa_g  = (const float*)d_in[7];
    const float* tdecay  = (const float*)d_in[8];
    const float* faaaa   = (const float*)d_in[9];
    const float* taaaaa  = (const float*)d_in[10];
    const float* maa_w1  = (const float*)d_in[11];
    const float* maa_w2  = (const float*)d_in[12];
    const float* dec_w1  = (const float*)d_in[13];
    const float* dec_w2  = (const float*)d_in[14];
    const float* aaa_w1  = (const float*)d_in[15];
    const float* aaa_w2  = (const float*)d_in[16];
    const float* kkk_w1  = (const float*)d_in[17];
    const float* kkk_w2  = (const float*)d_in[18];
    const float* gate_w1 = (const float*)d_in[19];
    const float* gate_w2 = (const float*)d_in[20];
    const float* w_key   = (const float*)d_in[21];
    const float* w_val   = (const float*)d_in[22];
    const float* w_rec   = (const float*)d_in[23];
    const float* w_out   = (const float*)d_in[24];
    const float* lnw     = (const float*)d_in[25];
    float* out = (float*)d_out;

    float* ws = 0;
    cudaGetSymbolAddress((void**)&ws, g_ws);

    float* TM = ws + WS_TM;
    float* XB = ws + WS_XB;                 // XB[n] = XB + n * BTCll
    float* H1 = ws + WS_H1;
    float* RIN = ws + WS_RIN;               // slices: r,w,k,v,am,bm
    float* KL = ws + WS_KL;
    float* AS = ws + WS_AS;
    float* GT = ws + WS_GT;
    float* Y  = ws + WS_Y;
    float* YG = ws + WS_YG;

    dim3 thr(256);

    // 1) tm = tanh(maa_w1 @ x)  : (B,384,T)
    gemm_k<<<dim3(Tt / 64, 384 / 64, Bb), thr>>>(
        maa_w1, 768, 1, 0,
        x, Tt, 1, CTll,
        TM, Tt, 1, 384LL * Tt,
        384, Tt, 768, EPI_TANH, 0, 0, 0);

    // 2) six mix projections -> xr..xg : xb_n = x * (1 + time_maa_n + w2_n @ tm_n)
    const float* tmaas[6] = {tmaa_r, tmaa_w, tmaa_k, tmaa_v, tmaa_a, tmaa_g};
    for (int n = 0; n < 6; n++) {
        gemm_k<<<dim3(Tt / 64, Cc / 64, Bb), thr>>>(
            maa_w2 + (long long)n * 64 * Cc, 1, Cc, 0,
            TM + (long long)n * 64 * Tt, Tt, 1, 384LL * Tt,
            XB + (long long)n * BTCll, Tt, 1, CTll,
            Cc, Tt, 64, EPI_MIX, tmaas[n], x, CTll);
    }

    // 3) grouped convs: r (from xr), k (from xk), v (from xv) -> (B,T,C) in RIN slices 0,2,3
    const float* cw[3]  = {w_rec, w_key, w_val};
    const int    cxb[3] = {0, 2, 3};
    const int    cri[3] = {0, 2, 3};
    for (int q = 0; q < 3; q++) {
        for (int g2 = 0; g2 < 2; g2++) {
            gemm_k<<<dim3(Tt / 64, 384 / 64, Bb), thr>>>(
                cw[q] + (long long)g2 * 384 * 384, 384, 1, 0,
                XB + (long long)cxb[q] * BTCll + (long long)g2 * 384 * Tt, Tt, 1, CTll,
                RIN + (long long)cri[q] * BTCll + g2 * 384, 1, Cc, CTll,
                384, Tt, 384, EPI_NONE, 0, 0, 0);
        }
    }

    // 4) decay lora: h = tanh(dec_w1 @ xw); wdec = exp(-exp(-softplus(-(td + dec_w2@h)) - 0.5)) -> RIN slice 1
    gemm_k<<<dim3(Tt / 64, 1, Bb), thr>>>(
        dec_w1, 768, 1, 0,
        XB + 1 * BTCll, Tt, 1, CTll,
        H1, Tt, 1, 64LL * Tt,
        64, Tt, 768, EPI_TANH, 0, 0, 0);
    gemm_k<<<dim3(Tt / 64, Cc / 64, Bb), thr>>>(
        dec_w2, 64, 1, 0,
        H1, Tt, 1, 64LL * Tt,
        RIN + 1 * BTCll, 1, Cc, CTll,
        Cc, Tt, 64, EPI_DECAY, tdecay, 0, 0);

    // 5) kkk lora (input xk) -> KL
    gemm_k<<<dim3(Tt / 64, 1, Bb), thr>>>(
        kkk_w1, 768, 1, 0,
        XB + 2 * BTCll, Tt, 1, CTll,
        H1, Tt, 1, 64LL * Tt,
        64, Tt, 768, EPI_TANH, 0, 0, 0);
    gemm_k<<<dim3(Tt / 64, Cc / 64, Bb), thr>>>(
        kkk_w2, 64, 1, 0,
        H1, Tt, 1, 64LL * Tt,
        KL, 1, Cc, CTll,
        Cc, Tt, 64, EPI_NONE, 0, 0, 0);

    // 6) aaa lora (input xa) -> AS = sigmoid(time_aaaaa + lora)
    gemm_k<<<dim3(Tt / 64, 1, Bb), thr>>>(
        aaa_w1, 768, 1, 0,
        XB + 4 * BTCll, Tt, 1, CTll,
        H1, Tt, 1, 64LL * Tt,
        64, Tt, 768, EPI_TANH, 0, 0, 0);
    gemm_k<<<dim3(Tt / 64, Cc / 64, Bb), thr>>>(
        aaa_w2, 64, 1, 0,
        H1, Tt, 1, 64LL * Tt,
        AS, 1, Cc, CTll,
        Cc, Tt, 64, EPI_SIG, taaaaa, 0, 0);

    // 7) gate lora (input xg) -> GT
    gemm_k<<<dim3(Tt / 64, 192 / 64, Bb), thr>>>(
        gate_w1, 768, 1, 0,
        XB + 5 * BTCll, Tt, 1, CTll,
        H1, Tt, 1, 192LL * Tt,
        192, Tt, 768, EPI_TANH, 0, 0, 0);
    gemm_k<<<dim3(Tt / 64, Cc / 64, Bb), thr>>>(
        gate_w2, 192, 1, 0,
        H1, Tt, 1, 192LL * Tt,
        GT, 1, Cc, CTll,
        Cc, Tt, 192, EPI_NONE, 0, 0, 0);

    // 8) E1: kk = normalize(k + kl) per head; am = -kk; bm = kk * asig
    e1_k<<<(Bb * Tt * Hh) / 8, 256>>>(RIN + 2 * BTCll, KL, AS,
                                      RIN + 4 * BTCll, RIN + 5 * BTCll);

    // 9) WKV7 recurrence -> Y
    wkv7_k<<<Bb * Hh * RS, 64>>>(RIN, Y);

    // 10) E2: RMSNorm + rk*v, gate multiply -> YG
    e2_k<<<Bb * Tt, 768>>>(Y, RIN, RIN + 2 * BTCll, RIN + 3 * BTCll,
                           GT, faaaa, lnw, YG);

    // 11) output grouped conv: (B,T,C) -> (B,C,T)
    for (int g2 = 0; g2 < 2; g2++) {
        gemm_k<<<dim3(Tt / 64, 384 / 64, Bb), thr>>>(
            w_out + (long long)g2 * 384 * 384, 384, 1, 0,
            YG + g2 * 384, 1, Cc, CTll,
            out + (long long)g2 * 384 * Tt, Tt, 1, CTll,
            384, Tt, 384, EPI_NONE, 0, 0, 0);
    }
}

// round 2
// speedup vs baseline: 1.1215x; 1.1215x over previous
#include <cuda_runtime.h>
#include <math.h>

#define Bb 2
#define Tt 2048
#define Cc 768
#define Hh 12

typedef unsigned long long ull;

static const long long CTll  = (long long)Cc * Tt;          // per-batch (C,T) plane
static const long long BTCll = (long long)Bb * Tt * Cc;     // full (B,T,C) tensor

// ---------------- workspace ----------------
#define WS_TM 0LL
#define WS_XB 1572864LL
#define WS_H1 20447232LL
#define WS_RIN 21233664LL
#define WS_KL 40108032LL
#define WS_AS 43253760LL
#define WS_GT 46399488LL
#define WS_Y  49545216LL
#define WS_YG 52690944LL
__device__ float g_ws[55836672];

// ---------------- f32x2 helpers ----------------
__device__ __forceinline__ void fma2(ull &d, ull a, ull b) {
    asm("fma.rn.f32x2 %0, %1, %2, %0;" : "+l"(d) : "l"(a), "l"(b));
}
__device__ __forceinline__ ull mul2(ull a, ull b) {
    ull d; asm("mul.rn.f32x2 %0, %1, %2;" : "=l"(d) : "l"(a), "l"(b)); return d;
}
__device__ __forceinline__ ull pk2(float v) {
    ull r; unsigned u = __float_as_uint(v);
    asm("mov.b64 %0, {%1, %1};" : "=l"(r) : "r"(u));
    return r;
}
__device__ __forceinline__ float lo2(ull p) { return __uint_as_float((unsigned)p); }
__device__ __forceinline__ float hi2(ull p) { return __uint_as_float((unsigned)(p >> 32)); }

// ---------------- GEMM with z-offset table ----------------
enum { EPI_NONE = 0, EPI_TANH = 1, EPI_MIX = 2, EPI_DECAY = 3, EPI_SIG = 4 };

struct ZMap {
    long long a[12], b[12], o[12], x1[12], x2[12];
    int epi[12];
};

#define LOAD_TILES(kt) do { \
    if (sAK == 1) { \
        const float* ap_ = A + (long long)(m0 + amr) * sAM + (kt) * 16 + ako; \
        ra0 = *(const float4*)ap_; ra1 = *(const float4*)(ap_ + 4); \
    } else { \
        const float* ap_ = A + (long long)((kt) * 16 + akr) * sAK + m0 + amo; \
        ra0 = *(const float4*)ap_; ra1 = *(const float4*)(ap_ + 4); \
    } \
    if (sBN == 1) { \
        const float* bp_ = Bm + (long long)((kt) * 16 + bkr) * sBK + n0 + bno; \
        rb0 = *(const float4*)bp_; rb1 = *(const float4*)(bp_ + 4); \
    } else { \
        const float* bp_ = Bm + (long long)(n0 + bnr) * sBN + (kt) * 16 + bko; \
        rb0 = *(const float4*)bp_; rb1 = *(const float4*)(bp_ + 4); \
    } \
} while (0)

#define STORE_TILES(bf) do { \
    if (sAK == 1) { \
        As[bf][ako+0][amr] = ra0.x; As[bf][ako+1][amr] = ra0.y; \
        As[bf][ako+2][amr] = ra0.z; As[bf][ako+3][amr] = ra0.w; \
        As[bf][ako+4][amr] = ra1.x; As[bf][ako+5][amr] = ra1.y; \
        As[bf][ako+6][amr] = ra1.z; As[bf][ako+7][amr] = ra1.w; \
    } else { \
        *(float4*)&As[bf][akr][amo] = ra0; *(float4*)&As[bf][akr][amo+4] = ra1; \
    } \
    if (sBN == 1) { \
        *(float4*)&Bs[bf][bkr][bno] = rb0; *(float4*)&Bs[bf][bkr][bno+4] = rb1; \
    } else { \
        Bs[bf][bko+0][bnr] = rb0.x; Bs[bf][bko+1][bnr] = rb0.y; \
        Bs[bf][bko+2][bnr] = rb0.z; Bs[bf][bko+3][bnr] = rb0.w; \
        Bs[bf][bko+4][bnr] = rb1.x; Bs[bf][bko+5][bnr] = rb1.y; \
        Bs[bf][bko+6][bnr] = rb1.z; Bs[bf][bko+7][bnr] = rb1.w; \
    } \
} while (0)

__global__ __launch_bounds__(128) void gemm_k(
    const float* __restrict__ A, int sAM, int sAK,
    const float* __restrict__ Bm, int sBK, int sBN,
    float* __restrict__ O, int sOM, int sON,
    int M, int N, int K,
    const float* __restrict__ aux1, const float* __restrict__ aux2,
    ZMap zm)
{
    int z = blockIdx.z;
    A  += zm.a[z];
    Bm += zm.b[z];
    O  += zm.o[z];
    const float* p1 = aux1 ? aux1 + zm.x1[z] : (const float*)0;
    const float* x2 = aux2 ? aux2 + zm.x2[z] : (const float*)0;
    int epi = zm.epi[z];

    __shared__ __align__(16) float As[2][16][68];
    __shared__ __align__(16) float Bs[2][16][68];

    const int tid = threadIdx.x;
    const int m0 = blockIdx.y * 64, n0 = blockIdx.x * 64;
    const int tn = tid & 15, tm = tid >> 4;

    const int amr = tid >> 1, ako = (tid & 1) * 8;   // A row-major map
    const int akr = tid >> 3, amo = (tid & 7) * 8;   // A col-major map
    const int bkr = tid >> 3, bno = (tid & 7) * 8;   // B n-contiguous map
    const int bnr = tid >> 1, bko = (tid & 1) * 8;   // B k-contiguous map

    float4 ra0, ra1, rb0, rb1;

    ull acc[4][4];
#pragma unroll
    for (int i = 0; i < 4; i++)
#pragma unroll
        for (int j = 0; j < 4; j++) acc[i][j] = 0ull;

    const int nk = K >> 4;
    LOAD_TILES(0);
    STORE_TILES(0);
    __syncthreads();

    for (int kt = 0; kt < nk; kt++) {
        int buf = kt & 1;
        if (kt + 1 < nk) LOAD_TILES(kt + 1);
#pragma unroll
        for (int k = 0; k < 16; k++) {
            ulonglong2 pa01 = *(const ulonglong2*)&As[buf][k][tm * 8];
            ulonglong2 pa23 = *(const ulonglong2*)&As[buf][k][tm * 8 + 4];
            float4 bv = *(const float4*)&Bs[buf][k][tn * 4];
            ull pb0 = pk2(bv.x), pb1 = pk2(bv.y), pb2 = pk2(bv.z), pb3 = pk2(bv.w);
            fma2(acc[0][0], pa01.x, pb0); fma2(acc[0][1], pa01.x, pb1);
            fma2(acc[0][2], pa01.x, pb2); fma2(acc[0][3], pa01.x, pb3);
            fma2(acc[1][0], pa01.y, pb0); fma2(acc[1][1], pa01.y, pb1);
            fma2(acc[1][2], pa01.y, pb2); fma2(acc[1][3], pa01.y, pb3);
            fma2(acc[2][0], pa23.x, pb0); fma2(acc[2][1], pa23.x, pb1);
            fma2(acc[2][2], pa23.x, pb2); fma2(acc[2][3], pa23.x, pb3);
            fma2(acc[3][0], pa23.y, pb0); fma2(acc[3][1], pa23.y, pb1);
            fma2(acc[3][2], pa23.y, pb2); fma2(acc[3][3], pa23.y, pb3);
        }
        if (kt + 1 < nk) STORE_TILES(buf ^ 1);
        __syncthreads();
    }

    float vout[8][4];
#pragma unroll
    for (int mp = 0; mp < 4; mp++)
#pragma unroll
        for (int j = 0; j < 4; j++) {
            vout[2 * mp][j]     = lo2(acc[mp][j]);
            vout[2 * mp + 1][j] = hi2(acc[mp][j]);
        }

#pragma unroll
    for (int r = 0; r < 8; r++) {
        int m = m0 + tm * 8 + r;
#pragma unroll
        for (int j = 0; j < 4; j++) {
            int n = n0 + tn * 4 + j;
            float v = vout[r][j];
            if (epi == EPI_TANH) {
                v = tanhf(v);
            } else if (epi == EPI_MIX) {
                v = x2[(long long)m * N + n] * (1.f + p1[m] + v);
            } else if (epi == EPI_DECAY) {
                float u = -(p1[m] + v);
                float sp = fmaxf(u, 0.f) + log1pf(expf(-fabsf(u)));
                v = expf(-expf(-sp - 0.5f));
            } else if (epi == EPI_SIG) {
                v = 1.f / (1.f + expf(-(p1[m] + v)));
            }
            vout[r][j] = v;
        }
    }

    if (sON == 1) {
#pragma unroll
        for (int r = 0; r < 8; r++) {
            float4 w4 = make_float4(vout[r][0], vout[r][1], vout[r][2], vout[r][3]);
            *(float4*)(O + (long long)(m0 + tm * 8 + r) * sOM + n0 + tn * 4) = w4;
        }
    } else {
#pragma unroll
        for (int j = 0; j < 4; j++) {
            long long nb = (long long)(n0 + tn * 4 + j) * sON + m0 + tm * 8;
            *(float4*)(O + nb)     = make_float4(vout[0][j], vout[1][j], vout[2][j], vout[3][j]);
            *(float4*)(O + nb + 4) = make_float4(vout[4][j], vout[5][j], vout[6][j], vout[7][j]);
        }
    }
}

// ---------------- E1: kk normalize, build a/b mats ----------------
__global__ __launch_bounds__(256) void e1_k(
    const float* __restrict__ kc, const float* __restrict__ kl,
    const float* __restrict__ asig, float* __restrict__ am, float* __restrict__ bm)
{
    int gw = (int)((blockIdx.x * blockDim.x + threadIdx.x) >> 5);
    int lane = threadIdx.x & 31;
    long long base = (long long)gw * 64;
    float k1 = kc[base + lane]      + kl[base + lane];
    float k2 = kc[base + lane + 32] + kl[base + lane + 32];
    float ss = k1 * k1 + k2 * k2;
#pragma unroll
    for (int o = 16; o; o >>= 1) ss += __shfl_xor_sync(0xffffffffu, ss, o);
    float inv = 1.f / fmaxf(sqrtf(ss), 1e-12f);
    float n1 = k1 * inv, n2 = k2 * inv;
    am[base + lane]      = -n1;
    am[base + lane + 32] = -n2;
    bm[base + lane]      = n1 * asig[base + lane];
    bm[base + lane + 32] = n2 * asig[base + lane + 32];
}

// ---------------- WKV7 recurrence (f32x2, pipelined sa) ----------------
#define RS 4
__global__ __launch_bounds__(64) void wkv7_k(const float* __restrict__ rin, float* __restrict__ y)
{
    int blk = blockIdx.x;
    int rs = blk & 3;
    int bh = blk >> 2;
    int b = bh / Hh, h = bh % Hh;
    long long base = (long long)b * Tt * Cc + (long long)h * 64;

    int tid = threadIdx.x;
    int lr = tid >> 2, jc = tid & 3;
    int i = rs * 16 + lr;
    int jb = jc << 4;

    __shared__ __align__(16) float sh[2][384];

#pragma unroll
    for (int q = 0; q < 6; q++)
        sh[0][q * 64 + tid] = rin[(long long)q * BTCll + base + tid];
    __syncthreads();

    ull S2[8];
#pragma unroll
    for (int u = 0; u < 8; u++) S2[u] = 0ull;
    float sa = 0.f;

    for (int t = 0; t < Tt; t++) {
        int cur = t & 1, nxt = cur ^ 1;
        float pf[6];
        if (t + 1 < Tt) {
            long long off = base + (long long)(t + 1) * Cc;
#pragma unroll
            for (int q = 0; q < 6; q++)
                pf[q] = rin[(long long)q * BTCll + off + tid];
        } else {
#pragma unroll
            for (int q = 0; q < 6; q++) pf[q] = 0.f;
        }

        const float* sb = &sh[cur][0];
        float vi = sb[3 * 64 + i];
        ull vi2 = pk2(vi), sa2 = pk2(sa);

        const ulonglong2* wp = (const ulonglong2*)(sb + 1 * 64 + jb);
        const ulonglong2* kp = (const ulonglong2*)(sb + 2 * 64 + jb);
        const ulonglong2* bp = (const ulonglong2*)(sb + 5 * 64 + jb);
        const ulonglong2* rp = (const ulonglong2*)(sb + 0 * 64 + jb);

        // update S: S = S*w + sa*b + vi*k
#pragma unroll
        for (int q = 0; q < 4; q++) {
            ulonglong2 wv = wp[q], kv = kp[q], bv = bp[q];
            ull d0 = mul2(vi2, kv.x);
            fma2(d0, sa2, bv.x);
            fma2(d0, S2[2 * q], wv.x);
            S2[2 * q] = d0;
            ull d1 = mul2(vi2, kv.y);
            fma2(d1, sa2, bv.y);
            fma2(d1, S2[2 * q + 1], wv.y);
            S2[2 * q + 1] = d1;
        }

        // y partials
        ull ya = 0ull, yb = 0ull;
#pragma unroll
        for (int q = 0; q < 4; q++) {
            ulonglong2 rv = rp[q];
            fma2(ya, S2[2 * q], rv.x);
            fma2(yb, S2[2 * q + 1], rv.y);
        }

        // stage t+1
        float* sn = &sh[nxt][0];
#pragma unroll
        for (int q = 0; q < 6; q++) sn[q * 64 + tid] = pf[q];
        __syncthreads();

        // sa partials for next step (a_{t+1})
        const ulonglong2* ap = (const ulonglong2*)(&sh[nxt][4 * 64 + jb]);
        ull za = 0ull, zb = 0ull;
#pragma unroll
        for (int q = 0; q < 4; q++) {
            ulonglong2 av = ap[q];
            fma2(za, S2[2 * q], av.x);
            fma2(zb, S2[2 * q + 1], av.y);
        }

        float yv = (lo2(ya) + hi2(ya)) + (lo2(yb) + hi2(yb));
        float sv = (lo2(za) + hi2(za)) + (lo2(zb) + hi2(zb));
        yv += __shfl_xor_sync(0xffffffffu, yv, 1);
        sv += __shfl_xor_sync(0xffffffffu, sv, 1);
        yv += __shfl_xor_sync(0xffffffffu, yv, 2);
        sv += __shfl_xor_sync(0xffffffffu, sv, 2);
        sa = sv;
        if (jc == 0)
            y[base + (long long)t * Cc + i] = yv;
    }
}

// ---------------- E2: RMSNorm + rk*v + gate ----------------
__global__ __launch_bounds__(768) void e2_k(
    const float* __restrict__ y,
    const float* __restrict__ rr, const float* __restrict__ kk, const float* __restrict__ vv,
    const float* __restrict__ gg, const float* __restrict__ faaaa,
    const float* __restrict__ lnw, float* __restrict__ yg)
{
    long long base = (long long)blockIdx.x * Cc;
    int c = threadIdx.x;
    int w = c >> 5, h = c >> 6, j = c & 63, lane = c & 31;
    float yv = y[base + c];
    float rv = rr[base + c], kv = kk[base + c], vV = vv[base + c];
    float s1 = yv * yv;
    float s2 = rv * kv * faaaa[h * 64 + j];
#pragma unroll
    for (int o = 16; o; o >>= 1) {
        s1 += __shfl_xor_sync(0xffffffffu, s1, o);
        s2 += __shfl_xor_sync(0xffffffffu, s2, o);
    }
    __shared__ float sh1[24], sh2[24];
    if (lane == 0) { sh1[w] = s1; sh2[w] = s2; }
    __syncthreads();
    float tot = 0.f;
#pragma unroll
    for (int q = 0; q < 24; q++) tot += sh1[q];
    float scale = rsqrtf(tot * (1.f / 768.f) + 1e-5f);
    float rk = sh2[h * 2] + sh2[h * 2 + 1];
    float yo = yv * scale * lnw[c] + rk * vV;
    yg[base + c] = yo * gg[base + c];
}

// ---------------- launch ----------------
static inline long long pdiff(const void* p, const void* base) {
    return (long long)((const float*)p - (const float*)base);
}

extern "C" void kernel_launch(void* const* d_in, const int* in_sizes, int n_in,
                              void* d_out, int out_size)
{
    (void)in_sizes; (void)n_in; (void)out_size;
    const float* x       = (const float*)d_in[0];
    const float* tmaa_r  = (const float*)d_in[2];
    const float* tmaa_w  = (const float*)d_in[3];
    const float* tmaa_k  = (const float*)d_in[4];
    const float* tmaa_v  = (const float*)d_in[5];
    const float* tmaa_a  = (const float*)d_in[6];
    const float* tmaa_g  = (const float*)d_in[7];
    const float* tdecay  = (const float*)d_in[8];
    const float* faaaa   = (const float*)d_in[9];
    const float* taaaaa  = (const float*)d_in[10];
    const float* maa_w1  = (const float*)d_in[11];
    const float* maa_w2  = (const float*)d_in[12];
    const float* dec_w1  = (const float*)d_in[13];
    const float* dec_w2  = (const float*)d_in[14];
    const float* aaa_w1  = (const float*)d_in[15];
    const float* aaa_w2  = (const float*)d_in[16];
    const float* kkk_w1  = (const float*)d_in[17];
    const float* kkk_w2  = (const float*)d_in[18];
    const float* gate_w1 = (const float*)d_in[19];
    const float* gate_w2 = (const float*)d_in[20];
    const float* w_key   = (const float*)d_in[21];
    const float* w_val   = (const float*)d_in[22];
    const float* w_rec   = (const float*)d_in[23];
    const float* w_out   = (const float*)d_in[24];
    const float* lnw     = (const float*)d_in[25];
    float* out = (float*)d_out;

    float* ws = 0;
    cudaGetSymbolAddress((void**)&ws, g_ws);

    float* TM  = ws + WS_TM;
    float* XB  = ws + WS_XB;
    float* H1  = ws + WS_H1;
    float* RIN = ws + WS_RIN;
    float* KL  = ws + WS_KL;
    float* AS  = ws + WS_AS;
    float* GT  = ws + WS_GT;
    float* Y   = ws + WS_Y;
    float* YG  = ws + WS_YG;

    // 1) TM = tanh(maa_w1 @ x): M=384, K=768, z=2 batches
    {
        ZMap zm = {};
        for (int b = 0; b < 2; b++) {
            zm.b[b] = (long long)b * CTll;
            zm.o[b] = (long long)b * 384 * Tt;
            zm.epi[b] = EPI_TANH;
        }
        gemm_k<<<dim3(32, 6, 2), 128>>>(maa_w1, 768, 1, x, Tt, 1, TM, Tt, 1,
                                        384, 2048, 768, 0, 0, zm);
    }

    // 2) MIX fused: z = n*2 + b (12), M=768, K=64
    {
        ZMap zm = {};
        const float* tmaas[6] = {tmaa_r, tmaa_w, tmaa_k, tmaa_v, tmaa_a, tmaa_g};
        for (int n = 0; n < 6; n++)
            for (int b = 0; b < 2; b++) {
                int z = n * 2 + b;
                zm.a[z]  = (long long)n * 64 * Cc;
                zm.b[z]  = (long long)b * 384 * Tt + (long long)n * 64 * Tt;
                zm.o[z]  = (long long)n * BTCll + (long long)b * CTll;
                zm.x1[z] = pdiff(tmaas[n], tmaa_r);
                zm.x2[z] = (long long)b * CTll;
                zm.epi[z] = EPI_MIX;
            }
        gemm_k<<<dim3(32, 12, 12), 128>>>(maa_w2, 1, Cc, TM, Tt, 1, XB, Tt, 1,
                                          768, 2048, 64, tmaa_r, x, zm);
    }

    // 3) convs fused (r,k,v): z = q*4 + g*2 + b (12), M=384, K=384
    {
        ZMap zm = {};
        long long qd[3] = {0, pdiff(w_key, w_rec), pdiff(w_val, w_rec)};
        const int xbi[3] = {0, 2, 3};
        const int rio[3] = {0, 2, 3};
        for (int q = 0; q < 3; q++)
            for (int g = 0; g < 2; g++)
                for (int b = 0; b < 2; b++) {
                    int z = q * 4 + g * 2 + b;
                    zm.a[z] = qd[q] + (long long)g * 384 * 384;
                    zm.b[z] = (long long)xbi[q] * BTCll + (long long)b * CTll + (long long)g * 384 * Tt;
                    zm.o[z] = (long long)rio[q] * BTCll + (long long)b * Tt * Cc + g * 384;
                    zm.epi[z] = EPI_NONE;
                }
        gemm_k<<<dim3(32, 6, 12), 128>>>(w_rec, 384, 1, XB, Tt, 1, RIN, 1, Cc,
                                         384, 2048, 384, 0, 0, zm);
    }

    // 4) lora stage1 fused (dec,kkk,aaa): z = q*2 + b (6), M=64, K=768
    {
        ZMap zm = {};
        long long qd[3] = {0, pdiff(kkk_w1, dec_w1), pdiff(aaa_w1, dec_w1)};
        const int sl[3] = {1, 2, 4};
        for (int q = 0; q < 3; q++)
            for (int b = 0; b < 2; b++) {
                int z = q * 2 + b;
                zm.a[z] = qd[q];
                zm.b[z] = (long long)sl[q] * BTCll + (long long)b * CTll;
                zm.o[z] = (long long)q * (2LL * 64 * Tt) + (long long)b * 64 * Tt;
                zm.epi[z] = EPI_TANH;
            }
        gemm_k<<<dim3(32, 1, 6), 128>>>(dec_w1, 768, 1, XB, Tt, 1, H1, Tt, 1,
                                        64, 2048, 768, 0, 0, zm);
    }

    // 5) gate stage1: M=192, K=768 -> TM (reused)
    {
        ZMap zm = {};
        for (int b = 0; b < 2; b++) {
            zm.b[b] = 5LL * BTCll + (long long)b * CTll;
            zm.o[b] = (long long)b * 192 * Tt;
            zm.epi[b] = EPI_TANH;
        }
        gemm_k<<<dim3(32, 3, 2), 128>>>(gate_w1, 768, 1, XB, Tt, 1, TM, Tt, 1,
                                        192, 2048, 768, 0, 0, zm);
    }

    // 6) lora stage2 fused: z = q*2 + b (6), M=768, K=64, per-z epilogue
    {
        ZMap zm = {};
        long long qd[3] = {0, pdiff(kkk_w2, dec_w2), pdiff(aaa_w2, dec_w2)};
        long long od[3] = {WS_RIN + BTCll, WS_KL, WS_AS};
        const int ep[3] = {EPI_DECAY, EPI_NONE, EPI_SIG};
        long long xd[3] = {0, 0, pdiff(taaaaa, tdecay)};
        for (int q = 0; q < 3; q++)
            for (int b = 0; b < 2; b++) {
                int z = q * 2 + b;
                zm.a[z]  = qd[q];
                zm.b[z]  = (long long)q * (2LL * 64 * Tt) + (long long)b * 64 * Tt;
                zm.o[z]  = od[q] + (long long)b * Tt * Cc;
                zm.x1[z] = xd[q];
                zm.epi[z] = ep[q];
            }
        gemm_k<<<dim3(32, 12, 6), 128>>>(dec_w2, 64, 1, H1, Tt, 1, ws, 1, Cc,
                                         768, 2048, 64, tdecay, 0, zm);
    }

    // 7) gate stage2: M=768, K=192 -> GT
    {
        ZMap zm = {};
        for (int b = 0; b < 2; b++) {
            zm.b[b] = (long long)b * 192 * Tt;
            zm.o[b] = (long long)b * Tt * Cc;
            zm.epi[b] = EPI_NONE;
        }
        gemm_k<<<dim3(32, 12, 2), 128>>>(gate_w2, 192, 1, TM, Tt, 1, GT, 1, Cc,
                                         768, 2048, 192, 0, 0, zm);
    }

    // 8) E1
    e1_k<<<(Bb * Tt * Hh) / 8, 256>>>(RIN + 2 * BTCll, KL, AS,
                                      RIN + 4 * BTCll, RIN + 5 * BTCll);

    // 9) WKV7
    wkv7_k<<<Bb * Hh * RS, 64>>>(RIN, Y);

    // 10) E2
    e2_k<<<Bb * Tt, 768>>>(Y, RIN, RIN + 2 * BTCll, RIN + 3 * BTCll,
                           GT, faaaa, lnw, YG);

    // 11) output conv: z = g*2 + b (4), M=384, K=384
    {
        ZMap zm = {};
        for (int g = 0; g < 2; g++)
            for (int b = 0; b < 2; b++) {
                int z = g * 2 + b;
                zm.a[z] = (long long)g * 384 * 384;
                zm.b[z] = (long long)b * Tt * Cc + g * 384;
                zm.o[z] = (long long)b * CTll + (long long)g * 384 * Tt;
                zm.epi[z] = EPI_NONE;
            }
        gemm_k<<<dim3(32, 6, 4), 128>>>(w_out, 384, 1, YG, 1, Cc, out, Tt, 1,
                                        384, 2048, 384, 0, 0, zm);
    }
}